// round 2
// baseline (speedup 1.0000x reference)
#include <cuda_runtime.h>

// ---------------- problem constants ----------------
#define N_TOK   1024
#define TZ      128          // z channels
#define TD      64           // hidden dim
#define NB      38           // num bins
#define EPSF    1e-5f

// ---------------- kernel tiling ----------------
#define TM      32           // pairs (rows) per tile
#define THREADS 256
#define NBLOCKS 296          // 2 per SM on 148-SM B300 die (persistent)
#define ZSTR    132          // zs row stride (floats), padded
#define VSTR    68           // Vs row stride (floats), padded

typedef unsigned long long u64;

// preprocessed weights (written by prep kernel each launch; deterministic)
__device__ float g_W1[TZ * TD];   // [c][d] = Wz[d][c] * z_gamma[c]
__device__ float g_W2t[TD * TZ];  // [d][c] = Wu[c][d]
__device__ float g_S[TD];         // sum_c W1[c][d]
__device__ float g_T[TD];         // sum_c Wz[d][c] * z_beta[c]

// ---------------- packed f32x2 helpers ----------------
__device__ __forceinline__ u64 dup2(float x) {
    u64 r;
    asm("mov.b64 %0, {%1, %1};" : "=l"(r) : "r"(__float_as_int(x)));
    return r;
}
__device__ __forceinline__ void ffma2(u64 &acc, u64 a, u64 b) {
    asm("fma.rn.f32x2 %0, %1, %2, %0;" : "+l"(acc) : "l"(a), "l"(b));
}
__device__ __forceinline__ float2 unpk(u64 v) {
    unsigned lo, hi;
    asm("mov.b64 {%0, %1}, %2;" : "=r"(lo), "=r"(hi) : "l"(v));
    return make_float2(__uint_as_float(lo), __uint_as_float(hi));
}

// ---------------- prep kernel ----------------
__global__ void prep_kernel(const float* __restrict__ Wz, const float* __restrict__ zg,
                            const float* __restrict__ zb, const float* __restrict__ Wu) {
    int t = threadIdx.x;
    for (int s = t; s < TZ * TD; s += THREADS) {
        int c = s / TD, d = s % TD;
        g_W1[s] = Wz[d * TZ + c] * zg[c];
    }
    for (int s = t; s < TD * TZ; s += THREADS) {
        int d = s / TZ, c = s % TZ;
        g_W2t[s] = Wu[c * TD + d];
    }
    __syncthreads();
    if (t < TD) {
        float S = 0.f, T = 0.f;
        for (int c = 0; c < TZ; c++) {
            S += g_W1[c * TD + t];
            T += Wz[t * TZ + c] * zb[c];
        }
        g_S[t] = S;
        g_T[t] = T;
    }
}

// ---------------- main fused kernel ----------------
__global__ __launch_bounds__(THREADS, 2)
void token_distance_kernel(const float* __restrict__ z, const float* __restrict__ cc,
                           const float* __restrict__ tdm, const float* __restrict__ Wa,
                           const float* __restrict__ vgam, const float* __restrict__ vbet,
                           float* __restrict__ out) {
    extern __shared__ float sm[];
    float* W1s  = sm;                   // 8192 : [c][d]
    float* W2s  = W1s + TZ * TD;        // 8192 : [d][c]
    float* zs   = W2s + TD * TZ;        // TM*ZSTR
    float* Vs   = zs + TM * ZSTR;       // TM*VSTR
    float* Was  = Vs + TM * VSTR;       // NB*TD : [bin][d]
    float* Ss   = Was + NB * TD;        // 64
    float* Ts   = Ss + TD;              // 64
    float* vgs  = Ts + TD;              // 64
    float* vbs  = vgs + TD;             // 64
    float* m1s  = vbs + TD;             // 32
    float* rs1s = m1s + TM;             // 32
    float* m2s  = rs1s + TM;            // 32
    float* rs2s = m2s + TM;             // 32
    float* msks = rs2s + TM;            // 32
    int*   idxs = (int*)(msks + TM);    // 32

    const int t = threadIdx.x;

    // per-block weight staging (once; blocks are persistent)
    for (int s = t; s < TZ * TD; s += THREADS) W1s[s] = g_W1[s];
    for (int s = t; s < TD * TZ; s += THREADS) W2s[s] = g_W2t[s];
    for (int s = t; s < NB * TD; s += THREADS) {
        int k = s >> 6, d = s & 63;
        Was[s] = Wa[d * NB + k];
    }
    if (t < TD) {
        Ss[t] = g_S[t]; Ts[t] = g_T[t];
        vgs[t] = vgam[t]; vbs[t] = vbet[t];
    }

    const int tx = t & 15, ty = t >> 4;
    const int d0 = tx * 4;           // GEMM1 output cols (conflict-free groups)
    const int c0 = tx * 4;           // GEMM2 output cols (plus +64 group)
    const int r0 = ty * 2;           // 2 rows per thread
    const int rr = t >> 3, part = t & 7;   // stats mapping: 8 threads/row

    const int NTILES = (N_TOK * N_TOK) / TM;
    for (int tile = blockIdx.x; tile < NTILES; tile += gridDim.x) {
        const int base_p = tile * TM;
        __syncthreads();   // guard zs/Vs reuse across iterations

        // ---- coalesced z tile load ----
        const float4* zg4 = (const float4*)(z + (size_t)base_p * TZ);
        #pragma unroll
        for (int i = 0; i < 4; i++) {
            int e = i * THREADS + t;           // 0..1023 float4
            float4 v = zg4[e];
            int r = e >> 5, c4 = e & 31;
            *(float4*)&zs[r * ZSTR + c4 * 4] = v;
        }
        __syncthreads();

        // ---- row stats (LN1) + distance bin ----
        {
            float s = 0.f, q = 0.f;
            #pragma unroll
            for (int i = 0; i < 4; i++) {
                float4 v = *(const float4*)&zs[rr * ZSTR + part * 16 + i * 4];
                s += v.x + v.y + v.z + v.w;
                q += v.x * v.x + v.y * v.y + v.z * v.z + v.w * v.w;
            }
            #pragma unroll
            for (int o = 1; o < 8; o <<= 1) {
                s += __shfl_xor_sync(0xffffffffu, s, o);
                q += __shfl_xor_sync(0xffffffffu, q, o);
            }
            if (part == 0) {
                float m = s * (1.f / TZ);
                float var = fmaxf(q * (1.f / TZ) - m * m, 0.f);
                m1s[rr] = m;
                rs1s[rr] = rsqrtf(var + EPSF);
                int p = base_p + rr;
                int i0 = p >> 10, j0 = p & (N_TOK - 1);
                float dx = cc[i0 * 3 + 0] - cc[j0 * 3 + 0];
                float dy = cc[i0 * 3 + 1] - cc[j0 * 3 + 1];
                float dz = cc[i0 * 3 + 2] - cc[j0 * 3 + 2];
                float dist = sqrtf(dx * dx + dy * dy + dz * dz);
                int idx = 0;
                #pragma unroll
                for (int k = 0; k < NB - 1; k++) {
                    float b = (float)(3.25 + k * (47.5 / 36.0));
                    idx += (dist > b) ? 1 : 0;
                }
                idxs[rr] = idx;
                msks[rr] = tdm[p];
            }
        }
        __syncthreads();

        // ---- GEMM1: V[TM][TD] = z @ W1, packed f32x2, 2 rows x 4 cols/thread ----
        {
            u64 a00 = 0, a01 = 0, a10 = 0, a11 = 0;
            #pragma unroll 8
            for (int cb = 0; cb < TZ; cb += 4) {
                float4 z0 = *(const float4*)&zs[r0 * ZSTR + cb];
                float4 z1 = *(const float4*)&zs[(r0 + 1) * ZSTR + cb];
                #define G1STEP(K, ZC0, ZC1) { \
                    ulonglong2 w = *(const ulonglong2*)&W1s[(cb + K) * TD + d0]; \
                    u64 p0 = dup2(ZC0); u64 p1 = dup2(ZC1); \
                    ffma2(a00, w.x, p0); ffma2(a01, w.y, p0); \
                    ffma2(a10, w.x, p1); ffma2(a11, w.y, p1); }
                G1STEP(0, z0.x, z1.x)
                G1STEP(1, z0.y, z1.y)
                G1STEP(2, z0.z, z1.z)
                G1STEP(3, z0.w, z1.w)
                #undef G1STEP
            }
            // epilogue: fold LN1 affine + S,T + distance-bin column
            float2 q00 = unpk(a00), q01 = unpk(a01), q10 = unpk(a10), q11 = unpk(a11);
            float4 Sv = *(const float4*)&Ss[d0];
            float4 Tv = *(const float4*)&Ts[d0];
            {
                int r = r0;
                float m1 = m1s[r], r1 = rs1s[r], mk = msks[r];
                float4 wa = *(const float4*)&Was[idxs[r] * TD + d0];
                float4 res;
                res.x = r1 * (q00.x - m1 * Sv.x) + Tv.x + mk * wa.x;
                res.y = r1 * (q00.y - m1 * Sv.y) + Tv.y + mk * wa.y;
                res.z = r1 * (q01.x - m1 * Sv.z) + Tv.z + mk * wa.z;
                res.w = r1 * (q01.y - m1 * Sv.w) + Tv.w + mk * wa.w;
                *(float4*)&Vs[r * VSTR + d0] = res;
            }
            {
                int r = r0 + 1;
                float m1 = m1s[r], r1 = rs1s[r], mk = msks[r];
                float4 wa = *(const float4*)&Was[idxs[r] * TD + d0];
                float4 res;
                res.x = r1 * (q10.x - m1 * Sv.x) + Tv.x + mk * wa.x;
                res.y = r1 * (q10.y - m1 * Sv.y) + Tv.y + mk * wa.y;
                res.z = r1 * (q11.x - m1 * Sv.z) + Tv.z + mk * wa.z;
                res.w = r1 * (q11.y - m1 * Sv.w) + Tv.w + mk * wa.w;
                *(float4*)&Vs[r * VSTR + d0] = res;
            }
        }
        __syncthreads();

        // ---- stats2 (LN over 64, exact for the v+v doubling via 4*var) ----
        {
            float s = 0.f, q = 0.f;
            float4 a4 = *(const float4*)&Vs[rr * VSTR + part * 8];
            float4 b4 = *(const float4*)&Vs[rr * VSTR + part * 8 + 4];
            s = a4.x + a4.y + a4.z + a4.w + b4.x + b4.y + b4.z + b4.w;
            q = a4.x * a4.x + a4.y * a4.y + a4.z * a4.z + a4.w * a4.w
              + b4.x * b4.x + b4.y * b4.y + b4.z * b4.z + b4.w * b4.w;
            #pragma unroll
            for (int o = 1; o < 8; o <<= 1) {
                s += __shfl_xor_sync(0xffffffffu, s, o);
                q += __shfl_xor_sync(0xffffffffu, q, o);
            }
            if (part == 0) {
                float m = s * (1.f / TD);
                float var = fmaxf(q * (1.f / TD) - m * m, 0.f);
                m2s[rr] = m;
                rs2s[rr] = rsqrtf(4.f * var + EPSF);   // LN of (v+v): 2(v-m)/sqrt(4var+eps)
            }
        }
        __syncthreads();

        // ---- normalize + relu in place ----
        {
            float m = m2s[rr];
            float sc = 2.f * rs2s[rr];
            int db = part * 8;
            float4 a4 = *(const float4*)&Vs[rr * VSTR + db];
            float4 b4 = *(const float4*)&Vs[rr * VSTR + db + 4];
            a4.x = fmaxf(fmaf((a4.x - m) * sc, vgs[db + 0], vbs[db + 0]), 0.f);
            a4.y = fmaxf(fmaf((a4.y - m) * sc, vgs[db + 1], vbs[db + 1]), 0.f);
            a4.z = fmaxf(fmaf((a4.z - m) * sc, vgs[db + 2], vbs[db + 2]), 0.f);
            a4.w = fmaxf(fmaf((a4.w - m) * sc, vgs[db + 3], vbs[db + 3]), 0.f);
            b4.x = fmaxf(fmaf((b4.x - m) * sc, vgs[db + 4], vbs[db + 4]), 0.f);
            b4.y = fmaxf(fmaf((b4.y - m) * sc, vgs[db + 5], vbs[db + 5]), 0.f);
            b4.z = fmaxf(fmaf((b4.z - m) * sc, vgs[db + 6], vbs[db + 6]), 0.f);
            b4.w = fmaxf(fmaf((b4.w - m) * sc, vgs[db + 7], vbs[db + 7]), 0.f);
            *(float4*)&Vs[rr * VSTR + db] = a4;
            *(float4*)&Vs[rr * VSTR + db + 4] = b4;
        }
        __syncthreads();

        // ---- GEMM2: U[TM][TZ] = relu(Vn) @ W2t, 2 rows x 8 cols/thread ----
        {
            u64 b00 = 0, b01 = 0, b02 = 0, b03 = 0;
            u64 b10 = 0, b11 = 0, b12 = 0, b13 = 0;
            #pragma unroll 4
            for (int db = 0; db < TD; db += 4) {
                float4 v0 = *(const float4*)&Vs[r0 * VSTR + db];
                float4 v1 = *(const float4*)&Vs[(r0 + 1) * VSTR + db];
                #define G2STEP(K, VC0, VC1) { \
                    ulonglong2 wA = *(const ulonglong2*)&W2s[(db + K) * TZ + c0]; \
                    ulonglong2 wB = *(const ulonglong2*)&W2s[(db + K) * TZ + c0 + 64]; \
                    u64 p0 = dup2(VC0); u64 p1 = dup2(VC1); \
                    ffma2(b00, wA.x, p0); ffma2(b01, wA.y, p0); \
                    ffma2(b02, wB.x, p0); ffma2(b03, wB.y, p0); \
                    ffma2(b10, wA.x, p1); ffma2(b11, wA.y, p1); \
                    ffma2(b12, wB.x, p1); ffma2(b13, wB.y, p1); }
                G2STEP(0, v0.x, v1.x)
                G2STEP(1, v0.y, v1.y)
                G2STEP(2, v0.z, v1.z)
                G2STEP(3, v0.w, v1.w)
                #undef G2STEP
            }
            {
                float2 u0 = unpk(b00), u1 = unpk(b01), u2 = unpk(b02), u3 = unpk(b03);
                float* o = out + (size_t)(base_p + r0) * TZ;
                *(float4*)&o[c0]      = make_float4(u0.x, u0.y, u1.x, u1.y);
                *(float4*)&o[c0 + 64] = make_float4(u2.x, u2.y, u3.x, u3.y);
            }
            {
                float2 u0 = unpk(b10), u1 = unpk(b11), u2 = unpk(b12), u3 = unpk(b13);
                float* o = out + (size_t)(base_p + r0 + 1) * TZ;
                *(float4*)&o[c0]      = make_float4(u0.x, u0.y, u1.x, u1.y);
                *(float4*)&o[c0 + 64] = make_float4(u2.x, u2.y, u3.x, u3.y);
            }
        }
    }
}

// ---------------- launch ----------------
static const int SMEM_FLOATS =
    TZ * TD + TD * TZ + TM * ZSTR + TM * VSTR + NB * TD + 4 * TD + 6 * TM;

extern "C" void kernel_launch(void* const* d_in, const int* in_sizes, int n_in,
                              void* d_out, int out_size) {
    const float* z    = (const float*)d_in[0];   // (1,1024,1024,128)
    const float* cc   = (const float*)d_in[1];   // (1,1024,3)
    const float* tdm  = (const float*)d_in[2];   // (1,1024,1024)
    // d_in[3] = pair_mask (unused by reference)
    const float* Wz   = (const float*)d_in[4];   // (64,128)
    const float* Wa   = (const float*)d_in[5];   // (64,38)
    const float* Wu   = (const float*)d_in[6];   // (128,64)
    const float* zg   = (const float*)d_in[7];   // (128)
    const float* zb   = (const float*)d_in[8];   // (128)
    const float* vg   = (const float*)d_in[9];   // (64)
    const float* vb   = (const float*)d_in[10];  // (64)
    float* out = (float*)d_out;

    size_t smem_bytes = (size_t)SMEM_FLOATS * sizeof(float);
    cudaFuncSetAttribute(token_distance_kernel,
                         cudaFuncAttributeMaxDynamicSharedMemorySize, (int)smem_bytes);

    prep_kernel<<<1, THREADS>>>(Wz, zg, zb, Wu);
    token_distance_kernel<<<NBLOCKS, THREADS, smem_bytes>>>(z, cc, tdm, Wa, vg, vb, out);
}